// round 12
// baseline (speedup 1.0000x reference)
#include <cuda_runtime.h>
#include <cuda_fp16.h>
#include <cstdint>

#define N_     100000
#define M_     12
#define C_     2000
#define ORIG_  92
#define NBR_   41
#define KP_    48                     // padded K for HMMA (3 x k16)
#define F_     64
#define H_     128
#define EPS_   1e-5f
#define NM_    (N_*M_)

// smem strides (halfs) chosen for conflict-free fragment access
#define SA_STR 56
#define SC_STR 136
#define SMEM_GATED ((128*SA_STR + 128*SA_STR + 128*SC_STR)*2 + 256*4)
#define SAZ_STR 72
#define SMEM_Z  ((128*SAZ_STR + 128*SAZ_STR + 128*SC_STR)*2)

// ---------------- scratch (device globals; no allocations allowed) -----------
__device__ float  g_x[(size_t)N_*F_];          // 25.6 MB  atom features fp32 (pooling)
__device__ __half g_xh[(size_t)N_*F_];         // 12.8 MB  atom features fp16 (GEMM A)
__device__ __half g_zh[(size_t)N_*256];        // 51.2 MB  [x@Wself | x@Wnbr] fp16
__device__ __half g_gated[(size_t)NM_*128];    // 307.2 MB pre-activation gated (fp16)
__device__ __half g_nbrh[(size_t)NM_*KP_];     // 115.2 MB nbr_fea fp16, K padded to 48
__device__ __half g_WchT[128*KP_];             // per-layer conv weight (nbr part), [n][k] fp16
__device__ __half g_WbigT[256*64];             // per-layer packed weight, [n][k] fp16
__device__ float  g_ns[(size_t)N_*F_];         // 25.6 MB  nbr_sumed
__device__ float  g_sum1[128], g_sq1[128], g_s1[128], g_h1[128];
__device__ float  g_sum2[64],  g_sq2[64],  g_s2[64],  g_h2[64];
__device__ float  g_csum[C_*F_], g_cnt[C_], g_cm2[C_*F_], g_asum[C_*F_];

struct __align__(16) H8 { __half2 a,b,c,d; };

// ---------------- FFMA-only math helpers (zero MUFU) --------------------------
__device__ __forceinline__ float fast_rcp(float d){
    float y = __int_as_float(0x7EF311C3 - __float_as_int(d));
    y = y*(2.0f - d*y);
    y = y*(2.0f - d*y);
    return y;
}
__device__ __forceinline__ float tanh_acc(float x){
    float z  = fminf(fmaxf(x, -7.90531110763549805f), 7.90531110763549805f);
    float x2 = z*z;
    float p = fmaf(x2, -2.76076847742355e-16f, 2.00018790482477e-13f);
    p = fmaf(p, x2, -8.60467152213735e-11f);
    p = fmaf(p, x2,  5.12229709037114e-08f);
    p = fmaf(p, x2,  1.48572235717979e-05f);
    p = fmaf(p, x2,  6.37261928875436e-04f);
    p = fmaf(p, x2,  4.89352455891786e-03f);
    p *= z;
    float q = fmaf(x2, 1.19825839466702e-06f, 1.18534705686654e-04f);
    q = fmaf(q, x2, 2.26843463243900e-03f);
    q = fmaf(q, x2, 4.89352518554385e-03f);
    return p * fast_rcp(q);
}
__device__ __forceinline__ float sigmoid_acc(float x){
    return fmaf(tanh_acc(0.5f*x), 0.5f, 0.5f);
}

__device__ __forceinline__ void mma16816(float& c0,float& c1,float& c2,float& c3,
    uint32_t a0,uint32_t a1,uint32_t a2,uint32_t a3,uint32_t b0,uint32_t b1){
    asm volatile("mma.sync.aligned.m16n8k16.row.col.f32.f16.f16.f32 "
        "{%0,%1,%2,%3},{%4,%5,%6,%7},{%8,%9},{%0,%1,%2,%3};"
        : "+f"(c0),"+f"(c1),"+f"(c2),"+f"(c3)
        : "r"(a0),"r"(a1),"r"(a2),"r"(a3),"r"(b0),"r"(b1));
}

// ---------------- embedding: g_x/g_xh = atom_fea @ emb_W + emb_b --------------
__global__ __launch_bounds__(256) void k_embed(const float* __restrict__ A,
                                               const float* __restrict__ B,
                                               const float* __restrict__ bias){
    __shared__ float sA[64][ORIG_];
    __shared__ float sB[ORIG_][64];
    int bm = blockIdx.x*64, tid = threadIdx.x;
    for(int e=tid; e<64*ORIG_; e+=256){ int r=e/ORIG_, k=e%ORIG_; int gr=bm+r;
        sA[r][k] = (gr<N_) ? A[(size_t)gr*ORIG_ + k] : 0.f; }
    for(int e=tid; e<ORIG_*64; e+=256){ int k=e>>6, c=e&63; sB[k][c] = B[k*64+c]; }
    __syncthreads();
    int tx = tid&15, ty = tid>>4;
    float acc[4][4] = {};
    for(int k=0;k<ORIG_;k++){
        float4 bv = *(const float4*)&sB[k][tx*4];
        #pragma unroll
        for(int i=0;i<4;i++){
            float a = sA[ty*4+i][k];
            acc[i][0]+=a*bv.x; acc[i][1]+=a*bv.y; acc[i][2]+=a*bv.z; acc[i][3]+=a*bv.w;
        }
    }
    #pragma unroll
    for(int i=0;i<4;i++){
        int gr = bm + ty*4 + i;
        if(gr<N_){
            float4 v = make_float4(acc[i][0]+bias[tx*4+0], acc[i][1]+bias[tx*4+1],
                                   acc[i][2]+bias[tx*4+2], acc[i][3]+bias[tx*4+3]);
            *(float4*)&g_x[(size_t)gr*64 + tx*4] = v;
            *(__half2*)&g_xh[(size_t)gr*64 + tx*4]     = __floats2half2_rn(v.x,v.y);
            *(__half2*)&g_xh[(size_t)gr*64 + tx*4 + 2] = __floats2half2_rn(v.z,v.w);
        }
    }
}

// ---------------- one-time: nbr_fea -> fp16 padded [NM][48] -------------------
__global__ __launch_bounds__(256) void k_nbrh(const float* __restrict__ nbr_fea){
    size_t e = (size_t)blockIdx.x*256 + threadIdx.x;
    if(e < (size_t)NM_*KP_){
        size_t r = e / KP_; int k = (int)(e - r*KP_);
        g_nbrh[e] = __float2half(k < NBR_ ? nbr_fea[r*NBR_ + k] : 0.f);
    }
}

// -- build fp16 WbigT [256n][64k] + WcT [128n][48k], zero BN1 stats ------------
__global__ void k_prep(const float* __restrict__ conv_W, int L){
    int e = blockIdx.x*256 + threadIdx.x;       // 64 blocks * 256 = 16384
    const float* W = conv_W + (size_t)L*169*128;
    {   // WbigT: n in 0..255, k in 0..63
        int n = e>>6, kk = e&63;
        g_WbigT[e] = __float2half((n<128) ? W[kk*128 + n] : W[(64+kk)*128 + (n-128)]);
    }
    if(e < 128*KP_){
        int n = e / KP_, kk = e - n*KP_;
        const float* Wc = W + 128*128;
        g_WchT[e] = __float2half(kk < NBR_ ? Wc[kk*128 + n] : 0.f);
    }
    if(blockIdx.x==0 && threadIdx.x<128){ g_sum1[threadIdx.x]=0.f; g_sq1[threadIdx.x]=0.f; }
}

// ---- z = x @ Wbig (HMMA): 128 rows x 128 cols per block, K=64 ----------------
__global__ __launch_bounds__(256) void k_z(){
    extern __shared__ __half smem[];
    __half* sA  = smem;                      // [128][SAZ_STR]
    __half* sBT = smem + 128*SAZ_STR;        // [128][SAZ_STR] (n-major, k inner)
    __half* sC  = smem + 2*128*SAZ_STR;      // [128][SC_STR]
    int bm = blockIdx.x*128, cb = blockIdx.y*128, tid = threadIdx.x;
    {   // A tile: 128 rows x 64 halfs (128B rows) from g_xh
        for(int e=tid; e<128*8; e+=256){ int r=e>>3, u=e&7; int gr=bm+r;
            uint4 v = (gr<N_) ? ((const uint4*)(g_xh + (size_t)gr*64))[u]
                              : make_uint4(0,0,0,0);
            *(uint4*)&sA[r*SAZ_STR + u*8] = v; }
        const uint4* srcB = (const uint4*)(g_WbigT + (size_t)cb*64);
        for(int e=tid; e<128*8; e+=256){ int r=e>>3, u=e&7;
            *(uint4*)&sBT[r*SAZ_STR + u*8] = srcB[r*8+u]; }
    }
    __syncthreads();
    {   // each warp: 16 rows x 128 cols, K=64 (4 k16 steps)
        int w = tid>>5, lane = tid&31, g = lane>>2, t = lane&3;
        const __half* sAw = sA + (w*16)*SAZ_STR;
        uint32_t af[4][4];
        #pragma unroll
        for(int kt=0;kt<4;kt++){
            af[kt][0] = *(const uint32_t*)&sAw[ g   *SAZ_STR + kt*16 + 2*t];
            af[kt][1] = *(const uint32_t*)&sAw[(g+8)*SAZ_STR + kt*16 + 2*t];
            af[kt][2] = *(const uint32_t*)&sAw[ g   *SAZ_STR + kt*16 + 2*t + 8];
            af[kt][3] = *(const uint32_t*)&sAw[(g+8)*SAZ_STR + kt*16 + 2*t + 8];
        }
        #pragma unroll
        for(int nt=0;nt<16;nt++){
            float c0=0.f,c1=0.f,c2=0.f,c3=0.f;
            const __half* sBn = sBT + (nt*8+g)*SAZ_STR;
            #pragma unroll
            for(int kt=0;kt<4;kt++){
                uint32_t b0 = *(const uint32_t*)&sBn[kt*16 + 2*t];
                uint32_t b1 = *(const uint32_t*)&sBn[kt*16 + 2*t + 8];
                mma16816(c0,c1,c2,c3, af[kt][0],af[kt][1],af[kt][2],af[kt][3], b0,b1);
            }
            *(__half2*)&sC[(w*16+g  )*SC_STR + nt*8 + 2*t] = __floats2half2_rn(c0,c1);
            *(__half2*)&sC[(w*16+g+8)*SC_STR + nt*8 + 2*t] = __floats2half2_rn(c2,c3);
        }
    }
    __syncthreads();
    int tx = tid&15, ty = tid>>4, cg = tx*8;
    #pragma unroll
    for(int i=0;i<8;i++){
        int rl = ty*8 + i, gr = bm + rl;
        if(gr<N_)
            *(H8*)&g_zh[(size_t)gr*256 + cb + cg] = *(const H8*)&sC[rl*SC_STR + cg];
    }
}

// ---- gated = nbr_fea@W3 (HMMA) + z1[i] + z2h[idx] + b ; BN1 stats ------------
__global__ __launch_bounds__(256) void k_gated(const int* __restrict__ nbr_idx,
                                               const float* __restrict__ conv_b, int L){
    extern __shared__ __half smem[];
    __half* sA  = smem;                     // [128][SA_STR]
    __half* sBT = smem + 128*SA_STR;        // [128][SA_STR] (n-major, k inner)
    __half* sC  = smem + 2*128*SA_STR;      // [128][SC_STR]
    float* ssum = (float*)(smem + 2*128*SA_STR + 128*SC_STR);
    float* ssq  = ssum + 128;
    int bm = blockIdx.x*128, tid = threadIdx.x;
    {   // load A tile (128 x 48 halfs, contiguous 96B rows) and W^T tile
        const uint4* srcA = (const uint4*)(g_nbrh + (size_t)bm*KP_);
        for(int e=tid; e<128*6; e+=256){ int r=e/6, u=e-r*6;
            *(uint4*)&sA[r*SA_STR + u*8] = srcA[r*6+u]; }
        const uint4* srcB = (const uint4*)g_WchT;
        for(int e=tid; e<128*6; e+=256){ int r=e/6, u=e-r*6;
            *(uint4*)&sBT[r*SA_STR + u*8] = srcB[r*6+u]; }
        if(tid<128){ ssum[tid]=0.f; ssq[tid]=0.f; }
    }
    __syncthreads();
    {   // tensor-core GEMM: each warp 16 rows x 128 cols, K=48
        int w = tid>>5, lane = tid&31, g = lane>>2, t = lane&3;
        const __half* sAw = sA + (w*16)*SA_STR;
        uint32_t af[3][4];
        #pragma unroll
        for(int kt=0;kt<3;kt++){
            af[kt][0] = *(const uint32_t*)&sAw[ g   *SA_STR + kt*16 + 2*t];
            af[kt][1] = *(const uint32_t*)&sAw[(g+8)*SA_STR + kt*16 + 2*t];
            af[kt][2] = *(const uint32_t*)&sAw[ g   *SA_STR + kt*16 + 2*t + 8];
            af[kt][3] = *(const uint32_t*)&sAw[(g+8)*SA_STR + kt*16 + 2*t + 8];
        }
        #pragma unroll
        for(int nt=0;nt<16;nt++){
            float c0=0.f,c1=0.f,c2=0.f,c3=0.f;
            const __half* sBn = sBT + (nt*8+g)*SA_STR;
            #pragma unroll
            for(int kt=0;kt<3;kt++){
                uint32_t b0 = *(const uint32_t*)&sBn[kt*16 + 2*t];
                uint32_t b1 = *(const uint32_t*)&sBn[kt*16 + 2*t + 8];
                mma16816(c0,c1,c2,c3, af[kt][0],af[kt][1],af[kt][2],af[kt][3], b0,b1);
            }
            *(__half2*)&sC[(w*16+g  )*SC_STR + nt*8 + 2*t] = __floats2half2_rn(c0,c1);
            *(__half2*)&sC[(w*16+g+8)*SC_STR + nt*8 + 2*t] = __floats2half2_rn(c2,c3);
        }
    }
    __syncthreads();
    // ---- epilogue: add z1 + z2 + bias, store fp16, BN1 stats -----------------
    int tx = tid&15, ty = tid>>4;
    int cg = tx*8;
    float4 bba = *(const float4*)&conv_b[L*128 + cg];
    float4 bbb = *(const float4*)&conv_b[L*128 + cg + 4];
    float ps[8]={0,0,0,0,0,0,0,0}, pq[8]={0,0,0,0,0,0,0,0};
    #pragma unroll
    for(int i=0;i<8;i++){
        int rl  = ty*8 + i;                // local row
        int r   = bm + rl;                 // edge id; NM divisible by 128
        int ia  = r / 12;
        int nid = nbr_idx[r];
        H8 gm = *(const H8*)&sC[rl*SC_STR + cg];
        float2 m0 = __half22float2(gm.a), m1 = __half22float2(gm.b);
        float2 m2 = __half22float2(gm.c), m3 = __half22float2(gm.d);
        H8 z1 = *(const H8*)&g_zh[(size_t)ia*256 + cg];
        float2 z1a = __half22float2(z1.a), z1b = __half22float2(z1.b);
        float2 z1c = __half22float2(z1.c), z1d = __half22float2(z1.d);
        H8 zh = *(const H8*)&g_zh[(size_t)nid*256 + 128 + cg];
        float2 z2a = __half22float2(zh.a), z2b = __half22float2(zh.b);
        float2 z2c = __half22float2(zh.c), z2d = __half22float2(zh.d);
        float v[8];
        v[0]=m0.x+z1a.x+z2a.x+bba.x; v[1]=m0.y+z1a.y+z2a.y+bba.y;
        v[2]=m1.x+z1b.x+z2b.x+bba.z; v[3]=m1.y+z1b.y+z2b.y+bba.w;
        v[4]=m2.x+z1c.x+z2c.x+bbb.x; v[5]=m2.y+z1c.y+z2c.y+bbb.y;
        v[6]=m3.x+z1d.x+z2d.x+bbb.z; v[7]=m3.y+z1d.y+z2d.y+bbb.w;
        H8 h;
        h.a = __floats2half2_rn(v[0],v[1]);
        h.b = __floats2half2_rn(v[2],v[3]);
        h.c = __floats2half2_rn(v[4],v[5]);
        h.d = __floats2half2_rn(v[6],v[7]);
        *(H8*)&g_gated[(size_t)r*128 + cg] = h;
        #pragma unroll
        for(int j=0;j<8;j++){ ps[j]+=v[j]; pq[j]+=v[j]*v[j]; }
    }
    #pragma unroll
    for(int j=0;j<8;j++){
        ps[j] += __shfl_xor_sync(0xffffffffu, ps[j], 16);
        pq[j] += __shfl_xor_sync(0xffffffffu, pq[j], 16);
    }
    if((tid&16)==0){
        #pragma unroll
        for(int j=0;j<8;j++){ atomicAdd(&ssum[cg+j], ps[j]); atomicAdd(&ssq[cg+j], pq[j]); }
    }
    __syncthreads();
    if(tid<128){ atomicAdd(&g_sum1[tid], ssum[tid]); atomicAdd(&g_sq1[tid], ssq[tid]); }
}

// ---------------- finalize BN1 scale/shift; zero BN2 stats --------------------
__global__ void k_bn1fin(const float* __restrict__ bn1_g, const float* __restrict__ bn1_b, int L){
    int c = threadIdx.x;                  // 128 threads
    float inv  = 1.f/(float)NM_;
    float mean = g_sum1[c]*inv;
    float var  = g_sq1[c]*inv - mean*mean;
    float s    = bn1_g[L*128+c]*rsqrtf(var + EPS_);
    g_s1[c] = s; g_h1[c] = bn1_b[L*128+c] - mean*s;
    if(c<64){ g_sum2[c]=0.f; g_sq2[c]=0.f; }
}

// ---------------- gate+sum over M; BN2 stats (round-10 version) ---------------
__global__ __launch_bounds__(256) void k_gatesum(){
    int c2 = (threadIdx.x & 31)*2, g = threadIdx.x >> 5;     // col pair, atom group
    int a0 = blockIdx.x*64;
    float s1f0=g_s1[c2],    h1f0=g_h1[c2],    s1f1=g_s1[c2+1],    h1f1=g_h1[c2+1];
    float s1c0=g_s1[64+c2], h1c0=g_h1[64+c2], s1c1=g_s1[64+c2+1], h1c1=g_h1[64+c2+1];
    float ps0=0.f, pq0=0.f, ps1=0.f, pq1=0.f;
    for(int t=0;t<8;t++){
        int a = a0 + t*8 + g;
        if(a < N_){
            const __half* gp = g_gated + (size_t)a*12*128;
            float acc0 = 0.f, acc1 = 0.f;
            #pragma unroll
            for(int m=0;m<12;m++){
                float2 f = __half22float2(*(const __half2*)&gp[m*128 + c2]);
                float2 cc= __half22float2(*(const __half2*)&gp[m*128 + 64 + c2]);
                float yf0 = f.x*s1f0 + h1f0, yf1 = f.y*s1f1 + h1f1;
                float yc0 = cc.x*s1c0 + h1c0, yc1 = cc.y*s1c1 + h1c1;
                acc0 += sigmoid_acc(yf0) * tanh_acc(yc0);
                acc1 += sigmoid_acc(yf1) * tanh_acc(yc1);
            }
            *(float2*)&g_ns[(size_t)a*64 + c2] = make_float2(acc0, acc1);
            ps0 += acc0; pq0 += acc0*acc0;
            ps1 += acc1; pq1 += acc1*acc1;
        }
    }
    __shared__ float ssum[64], ssq[64];
    if(threadIdx.x<64){ ssum[threadIdx.x]=0.f; ssq[threadIdx.x]=0.f; }
    __syncthreads();
    atomicAdd(&ssum[c2], ps0);   atomicAdd(&ssq[c2], pq0);
    atomicAdd(&ssum[c2+1], ps1); atomicAdd(&ssq[c2+1], pq1);
    __syncthreads();
    if(threadIdx.x<64){ atomicAdd(&g_sum2[threadIdx.x], ssum[threadIdx.x]);
                        atomicAdd(&g_sq2 [threadIdx.x], ssq [threadIdx.x]); }
}

__global__ void k_bn2fin(const float* __restrict__ bn2_g, const float* __restrict__ bn2_b, int L){
    int c = threadIdx.x;                  // 64 threads
    float inv  = 1.f/(float)N_;
    float mean = g_sum2[c]*inv;
    float var  = g_sq2[c]*inv - mean*mean;
    float s    = bn2_g[L*64+c]*rsqrtf(var + EPS_);
    g_s2[c] = s; g_h2[c] = bn2_b[L*64+c] - mean*s;
}

// ---------------- x = tanh(x + bn2(nbr_sumed)), 4 elems/thread ----------------
__global__ __launch_bounds__(256) void k_update(float* __restrict__ xout){
    int base = (blockIdx.x*256 + threadIdx.x)*4;   // N*F = 6.4M = 6250*1024 exactly
    int c = base & 63;
    float4 xv = *(const float4*)&g_x[base];
    float4 nv = *(const float4*)&g_ns[base];
    float4 s2 = *(const float4*)&g_s2[c];
    float4 h2 = *(const float4*)&g_h2[c];
    float v0 = tanh_acc(xv.x + nv.x*s2.x + h2.x);
    float v1 = tanh_acc(xv.y + nv.y*s2.y + h2.y);
    float v2 = tanh_acc(xv.z + nv.z*s2.z + h2.z);
    float v3 = tanh_acc(xv.w + nv.w*s2.w + h2.w);
    *(float4*)&g_x[base] = make_float4(v0,v1,v2,v3);
    *(__half2*)&g_xh[base]     = __floats2half2_rn(v0,v1);
    *(__half2*)&g_xh[base + 2] = __floats2half2_rn(v2,v3);
    if(xout) *(float4*)&xout[base] = make_float4(v0,v1,v2,v3);
}

// ---------------- pooling -----------------------------------------------------
__global__ void k_zero_pool(){
    for(int i = blockIdx.x*256 + threadIdx.x; i < C_*F_; i += gridDim.x*256){
        g_csum[i]=0.f; g_asum[i]=0.f;
        if(i<C_) g_cnt[i]=0.f;
    }
}

// sorted crystal_ids -> run-length reduced atomics (16 consecutive atoms/thread)
__global__ __launch_bounds__(256) void k_pool1(const int* __restrict__ cid){
    int tx = threadIdx.x & 63, ty = threadIdx.x >> 6;      // col, atom group
    int aStart = blockIdx.x*64 + ty*16;
    if(aStart >= N_) return;
    int aEnd = min(aStart + 16, N_);
    int cur = cid[aStart];
    float acc = 0.f; int runlen = 0;
    for(int a=aStart; a<aEnd; a++){
        int id = cid[a];
        if(id != cur){
            atomicAdd(&g_csum[cur*64 + tx], acc);
            if(tx==0) atomicAdd(&g_cnt[cur], (float)runlen);
            acc = 0.f; runlen = 0; cur = id;
        }
        acc += g_x[(size_t)a*64 + tx];
        runlen++;
    }
    atomicAdd(&g_csum[cur*64 + tx], acc);
    if(tx==0) atomicAdd(&g_cnt[cur], (float)runlen);
}

__global__ void k_poolW3(const float* __restrict__ W3_W, const float* __restrict__ W3_b){
    __shared__ float cm[64];
    int cidx = blockIdx.x, t = threadIdx.x;     // 64 threads
    float cnt = fmaxf(g_cnt[cidx], 1.f);
    cm[t] = g_csum[cidx*64 + t] / cnt;
    __syncthreads();
    float acc = W3_b[t];
    #pragma unroll
    for(int k=0;k<64;k++) acc += cm[k]*W3_W[k*64 + t];
    g_cm2[cidx*64 + t] = tanh_acc(acc);
}

// 8 atoms per block (N = 12500*8 exactly); fast-path block reduce when the
// whole block is one crystal (cids sorted), else per-warp atomics.
__global__ __launch_bounds__(256) void k_att(const int* __restrict__ cid){
    __shared__ float sacc[8][64];
    int warp = threadIdx.x>>5, lane = threadIdx.x&31;
    int a = blockIdx.x*8 + warp;
    int id = cid[a];
    float x0 = g_x[(size_t)a*64 + lane],     x1 = g_x[(size_t)a*64 + 32 + lane];
    float c0 = g_cm2[id*64 + lane],          c1 = g_cm2[id*64 + 32 + lane];
    float p = x0*c0 + x1*c1;
    #pragma unroll
    for(int o=16;o;o>>=1) p += __shfl_xor_sync(0xffffffffu, p, o);
    float s = sigmoid_acc(p);
    int id0 = cid[blockIdx.x*8];
    int idL = cid[blockIdx.x*8 + 7];
    if(id0 == idL){
        sacc[warp][lane]      = s*x0;
        sacc[warp][32 + lane] = s*x1;
        __syncthreads();
        if(threadIdx.x < 64){
            float tot = 0.f;
            #pragma unroll
            for(int w=0;w<8;w++) tot += sacc[w][threadIdx.x];
            atomicAdd(&g_asum[id0*64 + threadIdx.x], tot);
        }
    }else{
        atomicAdd(&g_asum[id*64 + lane],      s*x0);
        atomicAdd(&g_asum[id*64 + 32 + lane], s*x1);
    }
}

__global__ void k_head(const float* __restrict__ fc_W, const float* __restrict__ fc_b,
                       const float* __restrict__ out_W, const float* __restrict__ out_b,
                       float* __restrict__ out){
    __shared__ float am[64];
    __shared__ float red[128];
    int cidx = blockIdx.x, t = threadIdx.x;     // 128 threads
    float cnt = fmaxf(g_cnt[cidx], 1.f);
    if(t<64) am[t] = g_asum[cidx*64 + t] / cnt;
    __syncthreads();
    float acc = fc_b[t];
    #pragma unroll
    for(int k=0;k<64;k++) acc += am[k]*fc_W[k*128 + t];
    float sp = (acc > 20.f) ? acc : log1pf(expf(acc));   // softplus
    red[t] = sp * out_W[t];
    __syncthreads();
    for(int s=64; s; s>>=1){ if(t<s) red[t]+=red[t+s]; __syncthreads(); }
    if(t==0) out[cidx] = red[0] + out_b[0];
}

// ---------------- launch ------------------------------------------------------
extern "C" void kernel_launch(void* const* d_in, const int* in_sizes, int n_in,
                              void* d_out, int out_size){
    const float* atom_fea = (const float*)d_in[0];
    const float* nbr_fea  = (const float*)d_in[1];
    const int*   nbr_idx  = (const int*)  d_in[2];
    const int*   cids     = (const int*)  d_in[3];
    const float* emb_W    = (const float*)d_in[4];
    const float* emb_b    = (const float*)d_in[5];
    const float* conv_W   = (const float*)d_in[6];
    const float* conv_b   = (const float*)d_in[7];
    const float* bn1_g    = (const float*)d_in[8];
    const float* bn1_b    = (const float*)d_in[9];
    const float* bn2_g    = (const float*)d_in[10];
    const float* bn2_b    = (const float*)d_in[11];
    const float* W3_W     = (const float*)d_in[12];
    const float* W3_b     = (const float*)d_in[13];
    const float* fc_W     = (const float*)d_in[14];
    const float* fc_b     = (const float*)d_in[15];
    const float* out_W    = (const float*)d_in[16];
    const float* out_b    = (const float*)d_in[17];

    float* out  = (float*)d_out;
    float* xout = nullptr;
    if(out_size >= C_ + N_*F_) xout = out + ((size_t)out_size - (size_t)N_*F_);

    cudaFuncSetAttribute(k_gated, cudaFuncAttributeMaxDynamicSharedMemorySize, SMEM_GATED);
    cudaFuncSetAttribute(k_z,     cudaFuncAttributeMaxDynamicSharedMemorySize, SMEM_Z);

    k_embed<<<1563,256>>>(atom_fea, emb_W, emb_b);
    k_nbrh <<<(int)(((size_t)NM_*KP_ + 255)/256),256>>>(nbr_fea);
    for(int L=0; L<3; L++){
        k_prep <<<64,256>>>(conv_W, L);
        k_z    <<<dim3(782,2),256,SMEM_Z>>>();
        k_gated<<<9375,256,SMEM_GATED>>>(nbr_idx, conv_b, L);
        k_bn1fin<<<1,128>>>(bn1_g, bn1_b, L);
        k_gatesum<<<1563,256>>>();
        k_bn2fin<<<1,64>>>(bn2_g, bn2_b, L);
        k_update<<<6250,256>>>((L==2) ? xout : nullptr);
    }
    k_zero_pool<<<512,256>>>();
    k_pool1 <<<1563,256>>>(cids);
    k_poolW3<<<2000,64>>>(W3_W, W3_b);
    k_att   <<<12500,256>>>(cids);
    k_head  <<<2000,128>>>(fc_W, fc_b, out_W, out_b, out);
}

// round 13
// speedup vs baseline: 1.4565x; 1.4565x over previous
#include <cuda_runtime.h>
#include <cuda_fp16.h>
#include <cstdint>

#define N_     100000
#define M_     12
#define C_     2000
#define ORIG_  92
#define NBR_   41
#define KP_    48                     // padded K for HMMA (3 x k16)
#define F_     64
#define H_     128
#define EPS_   1e-5f
#define NM_    (N_*M_)

// smem strides (halfs) chosen for conflict-free fragment access
#define SA_STR 56
#define SC_STR 136
#define SMEM_GATED ((128*SA_STR + 128*SA_STR + 128*SC_STR)*2 + 256*4)
#define SAZ_STR 72
#define SMEM_Z  ((128*SAZ_STR + 128*SAZ_STR + 128*SC_STR)*2)

// ---------------- scratch (device globals; no allocations allowed) -----------
__device__ float  g_x[(size_t)N_*F_];          // 25.6 MB  atom features fp32 (pooling)
__device__ __half g_xh[(size_t)N_*F_];         // 12.8 MB  atom features fp16 (GEMM A)
__device__ __half g_zh[(size_t)N_*256];        // 51.2 MB  [x@Wself | x@Wnbr] fp16
__device__ __half g_gated[(size_t)NM_*128];    // 307.2 MB pre-activation gated (fp16)
__device__ __half g_nbrh[(size_t)NM_*KP_];     // 115.2 MB nbr_fea fp16, K padded to 48
__device__ __half g_WchT[128*KP_];             // per-layer conv weight (nbr part), [n][k] fp16
__device__ __half g_WbigT[256*64];             // per-layer packed weight, [n][k] fp16
__device__ float  g_ns[(size_t)N_*F_];         // 25.6 MB  nbr_sumed
__device__ float  g_sum1[128], g_sq1[128], g_s1[128], g_h1[128];
__device__ float  g_sum2[64],  g_sq2[64],  g_s2[64],  g_h2[64];
__device__ float  g_csum[C_*F_], g_cnt[C_], g_cm2[C_*F_], g_asum[C_*F_];

struct __align__(16) H8 { __half2 a,b,c,d; };

// ---------------- FFMA-only math helpers (zero MUFU) --------------------------
__device__ __forceinline__ float fast_rcp(float d){
    float y = __int_as_float(0x7EF311C3 - __float_as_int(d));
    y = y*(2.0f - d*y);
    y = y*(2.0f - d*y);
    return y;
}
__device__ __forceinline__ float tanh_acc(float x){
    float z  = fminf(fmaxf(x, -7.90531110763549805f), 7.90531110763549805f);
    float x2 = z*z;
    float p = fmaf(x2, -2.76076847742355e-16f, 2.00018790482477e-13f);
    p = fmaf(p, x2, -8.60467152213735e-11f);
    p = fmaf(p, x2,  5.12229709037114e-08f);
    p = fmaf(p, x2,  1.48572235717979e-05f);
    p = fmaf(p, x2,  6.37261928875436e-04f);
    p = fmaf(p, x2,  4.89352455891786e-03f);
    p *= z;
    float q = fmaf(x2, 1.19825839466702e-06f, 1.18534705686654e-04f);
    q = fmaf(q, x2, 2.26843463243900e-03f);
    q = fmaf(q, x2, 4.89352518554385e-03f);
    return p * fast_rcp(q);
}
__device__ __forceinline__ float sigmoid_acc(float x){
    return fmaf(tanh_acc(0.5f*x), 0.5f, 0.5f);
}

__device__ __forceinline__ void mma16816(float& c0,float& c1,float& c2,float& c3,
    uint32_t a0,uint32_t a1,uint32_t a2,uint32_t a3,uint32_t b0,uint32_t b1){
    asm volatile("mma.sync.aligned.m16n8k16.row.col.f32.f16.f16.f32 "
        "{%0,%1,%2,%3},{%4,%5,%6,%7},{%8,%9},{%0,%1,%2,%3};"
        : "+f"(c0),"+f"(c1),"+f"(c2),"+f"(c3)
        : "r"(a0),"r"(a1),"r"(a2),"r"(a3),"r"(b0),"r"(b1));
}

// ---------------- embedding: g_x/g_xh = atom_fea @ emb_W + emb_b --------------
__global__ __launch_bounds__(256) void k_embed(const float* __restrict__ A,
                                               const float* __restrict__ B,
                                               const float* __restrict__ bias){
    __shared__ float sA[64][ORIG_];
    __shared__ float sB[ORIG_][64];
    int bm = blockIdx.x*64, tid = threadIdx.x;
    for(int e=tid; e<64*ORIG_; e+=256){ int r=e/ORIG_, k=e%ORIG_; int gr=bm+r;
        sA[r][k] = (gr<N_) ? A[(size_t)gr*ORIG_ + k] : 0.f; }
    for(int e=tid; e<ORIG_*64; e+=256){ int k=e>>6, c=e&63; sB[k][c] = B[k*64+c]; }
    __syncthreads();
    int tx = tid&15, ty = tid>>4;
    float acc[4][4] = {};
    for(int k=0;k<ORIG_;k++){
        float4 bv = *(const float4*)&sB[k][tx*4];
        #pragma unroll
        for(int i=0;i<4;i++){
            float a = sA[ty*4+i][k];
            acc[i][0]+=a*bv.x; acc[i][1]+=a*bv.y; acc[i][2]+=a*bv.z; acc[i][3]+=a*bv.w;
        }
    }
    #pragma unroll
    for(int i=0;i<4;i++){
        int gr = bm + ty*4 + i;
        if(gr<N_){
            float4 v = make_float4(acc[i][0]+bias[tx*4+0], acc[i][1]+bias[tx*4+1],
                                   acc[i][2]+bias[tx*4+2], acc[i][3]+bias[tx*4+3]);
            *(float4*)&g_x[(size_t)gr*64 + tx*4] = v;
            *(__half2*)&g_xh[(size_t)gr*64 + tx*4]     = __floats2half2_rn(v.x,v.y);
            *(__half2*)&g_xh[(size_t)gr*64 + tx*4 + 2] = __floats2half2_rn(v.z,v.w);
        }
    }
}

// ---------------- one-time: nbr_fea -> fp16 padded [NM][48] -------------------
__global__ __launch_bounds__(256) void k_nbrh(const float* __restrict__ nbr_fea){
    size_t e = (size_t)blockIdx.x*256 + threadIdx.x;
    if(e < (size_t)NM_*KP_){
        size_t r = e / KP_; int k = (int)(e - r*KP_);
        g_nbrh[e] = __float2half(k < NBR_ ? nbr_fea[r*NBR_ + k] : 0.f);
    }
}

// -- build fp16 WbigT [256n][64k] + WcT [128n][48k], zero BN1 stats ------------
__global__ void k_prep(const float* __restrict__ conv_W, int L){
    int e = blockIdx.x*256 + threadIdx.x;       // 64 blocks * 256 = 16384
    const float* W = conv_W + (size_t)L*169*128;
    {   // WbigT: n in 0..255, k in 0..63
        int n = e>>6, kk = e&63;
        g_WbigT[e] = __float2half((n<128) ? W[kk*128 + n] : W[(64+kk)*128 + (n-128)]);
    }
    if(e < 128*KP_){
        int n = e / KP_, kk = e - n*KP_;
        const float* Wc = W + 128*128;
        g_WchT[e] = __float2half(kk < NBR_ ? Wc[kk*128 + n] : 0.f);
    }
    if(blockIdx.x==0 && threadIdx.x<128){ g_sum1[threadIdx.x]=0.f; g_sq1[threadIdx.x]=0.f; }
}

// ---- z = x @ Wbig (HMMA): 128 rows x 128 cols per block, K=64 ----------------
__global__ __launch_bounds__(256) void k_z(){
    extern __shared__ __half smem[];
    __half* sA  = smem;                      // [128][SAZ_STR]
    __half* sBT = smem + 128*SAZ_STR;        // [128][SAZ_STR] (n-major, k inner)
    __half* sC  = smem + 2*128*SAZ_STR;      // [128][SC_STR]
    int bm = blockIdx.x*128, cb = blockIdx.y*128, tid = threadIdx.x;
    {   // A tile: 128 rows x 64 halfs (128B rows) from g_xh
        for(int e=tid; e<128*8; e+=256){ int r=e>>3, u=e&7; int gr=bm+r;
            uint4 v = (gr<N_) ? ((const uint4*)(g_xh + (size_t)gr*64))[u]
                              : make_uint4(0,0,0,0);
            *(uint4*)&sA[r*SAZ_STR + u*8] = v; }
        const uint4* srcB = (const uint4*)(g_WbigT + (size_t)cb*64);
        for(int e=tid; e<128*8; e+=256){ int r=e>>3, u=e&7;
            *(uint4*)&sBT[r*SAZ_STR + u*8] = srcB[r*8+u]; }
    }
    __syncthreads();
    {   // each warp: 16 rows x 128 cols, K=64 (4 k16 steps)
        int w = tid>>5, lane = tid&31, g = lane>>2, t = lane&3;
        const __half* sAw = sA + (w*16)*SAZ_STR;
        uint32_t af[4][4];
        #pragma unroll
        for(int kt=0;kt<4;kt++){
            af[kt][0] = *(const uint32_t*)&sAw[ g   *SAZ_STR + kt*16 + 2*t];
            af[kt][1] = *(const uint32_t*)&sAw[(g+8)*SAZ_STR + kt*16 + 2*t];
            af[kt][2] = *(const uint32_t*)&sAw[ g   *SAZ_STR + kt*16 + 2*t + 8];
            af[kt][3] = *(const uint32_t*)&sAw[(g+8)*SAZ_STR + kt*16 + 2*t + 8];
        }
        #pragma unroll
        for(int nt=0;nt<16;nt++){
            float c0=0.f,c1=0.f,c2=0.f,c3=0.f;
            const __half* sBn = sBT + (nt*8+g)*SAZ_STR;
            #pragma unroll
            for(int kt=0;kt<4;kt++){
                uint32_t b0 = *(const uint32_t*)&sBn[kt*16 + 2*t];
                uint32_t b1 = *(const uint32_t*)&sBn[kt*16 + 2*t + 8];
                mma16816(c0,c1,c2,c3, af[kt][0],af[kt][1],af[kt][2],af[kt][3], b0,b1);
            }
            *(__half2*)&sC[(w*16+g  )*SC_STR + nt*8 + 2*t] = __floats2half2_rn(c0,c1);
            *(__half2*)&sC[(w*16+g+8)*SC_STR + nt*8 + 2*t] = __floats2half2_rn(c2,c3);
        }
    }
    __syncthreads();
    int tx = tid&15, ty = tid>>4, cg = tx*8;
    #pragma unroll
    for(int i=0;i<8;i++){
        int rl = ty*8 + i, gr = bm + rl;
        if(gr<N_)
            *(H8*)&g_zh[(size_t)gr*256 + cb + cg] = *(const H8*)&sC[rl*SC_STR + cg];
    }
}

// ---- gated = nbr_fea@W3 (HMMA) + z1[i] + z2h[idx] + b ; BN1 stats ------------
__global__ __launch_bounds__(256) void k_gated(const int* __restrict__ nbr_idx,
                                               const float* __restrict__ conv_b, int L){
    extern __shared__ __half smem[];
    __half* sA  = smem;                     // [128][SA_STR]
    __half* sBT = smem + 128*SA_STR;        // [128][SA_STR] (n-major, k inner)
    __half* sC  = smem + 2*128*SA_STR;      // [128][SC_STR]
    float* ssum = (float*)(smem + 2*128*SA_STR + 128*SC_STR);
    float* ssq  = ssum + 128;
    int bm = blockIdx.x*128, tid = threadIdx.x;
    {   // load A tile (128 x 48 halfs, contiguous 96B rows) and W^T tile
        const uint4* srcA = (const uint4*)(g_nbrh + (size_t)bm*KP_);
        for(int e=tid; e<128*6; e+=256){ int r=e/6, u=e-r*6;
            *(uint4*)&sA[r*SA_STR + u*8] = srcA[r*6+u]; }
        const uint4* srcB = (const uint4*)g_WchT;
        for(int e=tid; e<128*6; e+=256){ int r=e/6, u=e-r*6;
            *(uint4*)&sBT[r*SA_STR + u*8] = srcB[r*6+u]; }
        if(tid<128){ ssum[tid]=0.f; ssq[tid]=0.f; }
    }
    __syncthreads();
    {   // tensor-core GEMM: each warp 16 rows x 128 cols, K=48
        int w = tid>>5, lane = tid&31, g = lane>>2, t = lane&3;
        const __half* sAw = sA + (w*16)*SA_STR;
        uint32_t af[3][4];
        #pragma unroll
        for(int kt=0;kt<3;kt++){
            af[kt][0] = *(const uint32_t*)&sAw[ g   *SA_STR + kt*16 + 2*t];
            af[kt][1] = *(const uint32_t*)&sAw[(g+8)*SA_STR + kt*16 + 2*t];
            af[kt][2] = *(const uint32_t*)&sAw[ g   *SA_STR + kt*16 + 2*t + 8];
            af[kt][3] = *(const uint32_t*)&sAw[(g+8)*SA_STR + kt*16 + 2*t + 8];
        }
        #pragma unroll
        for(int nt=0;nt<16;nt++){
            float c0=0.f,c1=0.f,c2=0.f,c3=0.f;
            const __half* sBn = sBT + (nt*8+g)*SA_STR;
            #pragma unroll
            for(int kt=0;kt<3;kt++){
                uint32_t b0 = *(const uint32_t*)&sBn[kt*16 + 2*t];
                uint32_t b1 = *(const uint32_t*)&sBn[kt*16 + 2*t + 8];
                mma16816(c0,c1,c2,c3, af[kt][0],af[kt][1],af[kt][2],af[kt][3], b0,b1);
            }
            *(__half2*)&sC[(w*16+g  )*SC_STR + nt*8 + 2*t] = __floats2half2_rn(c0,c1);
            *(__half2*)&sC[(w*16+g+8)*SC_STR + nt*8 + 2*t] = __floats2half2_rn(c2,c3);
        }
    }
    __syncthreads();
    // ---- epilogue: add z1 + z2 + bias, store fp16, BN1 stats -----------------
    int tx = tid&15, ty = tid>>4;
    int cg = tx*8;
    float4 bba = *(const float4*)&conv_b[L*128 + cg];
    float4 bbb = *(const float4*)&conv_b[L*128 + cg + 4];
    float ps[8]={0,0,0,0,0,0,0,0}, pq[8]={0,0,0,0,0,0,0,0};
    #pragma unroll
    for(int i=0;i<8;i++){
        int rl  = ty*8 + i;                // local row
        int r   = bm + rl;                 // edge id; NM divisible by 128
        int ia  = r / 12;
        int nid = nbr_idx[r];
        H8 gm = *(const H8*)&sC[rl*SC_STR + cg];
        float2 m0 = __half22float2(gm.a), m1 = __half22float2(gm.b);
        float2 m2 = __half22float2(gm.c), m3 = __half22float2(gm.d);
        H8 z1 = *(const H8*)&g_zh[(size_t)ia*256 + cg];
        float2 z1a = __half22float2(z1.a), z1b = __half22float2(z1.b);
        float2 z1c = __half22float2(z1.c), z1d = __half22float2(z1.d);
        H8 zh = *(const H8*)&g_zh[(size_t)nid*256 + 128 + cg];
        float2 z2a = __half22float2(zh.a), z2b = __half22float2(zh.b);
        float2 z2c = __half22float2(zh.c), z2d = __half22float2(zh.d);
        float v[8];
        v[0]=m0.x+z1a.x+z2a.x+bba.x; v[1]=m0.y+z1a.y+z2a.y+bba.y;
        v[2]=m1.x+z1b.x+z2b.x+bba.z; v[3]=m1.y+z1b.y+z2b.y+bba.w;
        v[4]=m2.x+z1c.x+z2c.x+bbb.x; v[5]=m2.y+z1c.y+z2c.y+bbb.y;
        v[6]=m3.x+z1d.x+z2d.x+bbb.z; v[7]=m3.y+z1d.y+z2d.y+bbb.w;
        H8 h;
        h.a = __floats2half2_rn(v[0],v[1]);
        h.b = __floats2half2_rn(v[2],v[3]);
        h.c = __floats2half2_rn(v[4],v[5]);
        h.d = __floats2half2_rn(v[6],v[7]);
        *(H8*)&g_gated[(size_t)r*128 + cg] = h;
        #pragma unroll
        for(int j=0;j<8;j++){ ps[j]+=v[j]; pq[j]+=v[j]*v[j]; }
    }
    #pragma unroll
    for(int j=0;j<8;j++){
        ps[j] += __shfl_xor_sync(0xffffffffu, ps[j], 16);
        pq[j] += __shfl_xor_sync(0xffffffffu, pq[j], 16);
    }
    if((tid&16)==0){
        #pragma unroll
        for(int j=0;j<8;j++){ atomicAdd(&ssum[cg+j], ps[j]); atomicAdd(&ssq[cg+j], pq[j]); }
    }
    __syncthreads();
    if(tid<128){ atomicAdd(&g_sum1[tid], ssum[tid]); atomicAdd(&g_sq1[tid], ssq[tid]); }
}

// ---------------- finalize BN1 scale/shift; zero BN2 stats --------------------
__global__ void k_bn1fin(const float* __restrict__ bn1_g, const float* __restrict__ bn1_b, int L){
    int c = threadIdx.x;                  // 128 threads
    float inv  = 1.f/(float)NM_;
    float mean = g_sum1[c]*inv;
    float var  = g_sq1[c]*inv - mean*mean;
    float s    = bn1_g[L*128+c]*rsqrtf(var + EPS_);
    g_s1[c] = s; g_h1[c] = bn1_b[L*128+c] - mean*s;
    if(c<64){ g_sum2[c]=0.f; g_sq2[c]=0.f; }
}

// ---------------- gate+sum over M; BN2 stats (round-10 version) ---------------
__global__ __launch_bounds__(256) void k_gatesum(){
    int c2 = (threadIdx.x & 31)*2, g = threadIdx.x >> 5;     // col pair, atom group
    int a0 = blockIdx.x*64;
    float s1f0=g_s1[c2],    h1f0=g_h1[c2],    s1f1=g_s1[c2+1],    h1f1=g_h1[c2+1];
    float s1c0=g_s1[64+c2], h1c0=g_h1[64+c2], s1c1=g_s1[64+c2+1], h1c1=g_h1[64+c2+1];
    float ps0=0.f, pq0=0.f, ps1=0.f, pq1=0.f;
    for(int t=0;t<8;t++){
        int a = a0 + t*8 + g;
        if(a < N_){
            const __half* gp = g_gated + (size_t)a*12*128;
            float acc0 = 0.f, acc1 = 0.f;
            #pragma unroll
            for(int m=0;m<12;m++){
                float2 f = __half22float2(*(const __half2*)&gp[m*128 + c2]);
                float2 cc= __half22float2(*(const __half2*)&gp[m*128 + 64 + c2]);
                float yf0 = f.x*s1f0 + h1f0, yf1 = f.y*s1f1 + h1f1;
                float yc0 = cc.x*s1c0 + h1c0, yc1 = cc.y*s1c1 + h1c1;
                acc0 += sigmoid_acc(yf0) * tanh_acc(yc0);
                acc1 += sigmoid_acc(yf1) * tanh_acc(yc1);
            }
            *(float2*)&g_ns[(size_t)a*64 + c2] = make_float2(acc0, acc1);
            ps0 += acc0; pq0 += acc0*acc0;
            ps1 += acc1; pq1 += acc1*acc1;
        }
    }
    __shared__ float ssum[64], ssq[64];
    if(threadIdx.x<64){ ssum[threadIdx.x]=0.f; ssq[threadIdx.x]=0.f; }
    __syncthreads();
    atomicAdd(&ssum[c2], ps0);   atomicAdd(&ssq[c2], pq0);
    atomicAdd(&ssum[c2+1], ps1); atomicAdd(&ssq[c2+1], pq1);
    __syncthreads();
    if(threadIdx.x<64){ atomicAdd(&g_sum2[threadIdx.x], ssum[threadIdx.x]);
                        atomicAdd(&g_sq2 [threadIdx.x], ssq [threadIdx.x]); }
}

__global__ void k_bn2fin(const float* __restrict__ bn2_g, const float* __restrict__ bn2_b, int L){
    int c = threadIdx.x;                  // 64 threads
    float inv  = 1.f/(float)N_;
    float mean = g_sum2[c]*inv;
    float var  = g_sq2[c]*inv - mean*mean;
    float s    = bn2_g[L*64+c]*rsqrtf(var + EPS_);
    g_s2[c] = s; g_h2[c] = bn2_b[L*64+c] - mean*s;
}

// ---------------- x = tanh(x + bn2(nbr_sumed)), 4 elems/thread ----------------
__global__ __launch_bounds__(256) void k_update(float* __restrict__ xout){
    int base = (blockIdx.x*256 + threadIdx.x)*4;   // N*F = 6.4M = 6250*1024 exactly
    int c = base & 63;
    float4 xv = *(const float4*)&g_x[base];
    float4 nv = *(const float4*)&g_ns[base];
    float4 s2 = *(const float4*)&g_s2[c];
    float4 h2 = *(const float4*)&g_h2[c];
    float v0 = tanh_acc(xv.x + nv.x*s2.x + h2.x);
    float v1 = tanh_acc(xv.y + nv.y*s2.y + h2.y);
    float v2 = tanh_acc(xv.z + nv.z*s2.z + h2.z);
    float v3 = tanh_acc(xv.w + nv.w*s2.w + h2.w);
    *(float4*)&g_x[base] = make_float4(v0,v1,v2,v3);
    *(__half2*)&g_xh[base]     = __floats2half2_rn(v0,v1);
    *(__half2*)&g_xh[base + 2] = __floats2half2_rn(v2,v3);
    if(xout) *(float4*)&xout[base] = make_float4(v0,v1,v2,v3);
}

// ---------------- pooling (round-10 versions) ---------------------------------
__global__ void k_zero_pool(){
    for(int i = blockIdx.x*256 + threadIdx.x; i < C_*F_; i += gridDim.x*256){
        g_csum[i]=0.f; g_asum[i]=0.f;
        if(i<C_) g_cnt[i]=0.f;
    }
}

__global__ __launch_bounds__(256) void k_pool1(const int* __restrict__ cid){
    int idx = blockIdx.x*256 + threadIdx.x;
    if(idx < N_*F_){
        int a = idx>>6, c = idx&63;
        int id = cid[a];
        atomicAdd(&g_csum[id*64 + c], g_x[idx]);
        if(c==0) atomicAdd(&g_cnt[id], 1.f);
    }
}

__global__ void k_poolW3(const float* __restrict__ W3_W, const float* __restrict__ W3_b){
    __shared__ float cm[64];
    int cidx = blockIdx.x, t = threadIdx.x;     // 64 threads
    float cnt = fmaxf(g_cnt[cidx], 1.f);
    cm[t] = g_csum[cidx*64 + t] / cnt;
    __syncthreads();
    float acc = W3_b[t];
    #pragma unroll
    for(int k=0;k<64;k++) acc += cm[k]*W3_W[k*64 + t];
    g_cm2[cidx*64 + t] = tanh_acc(acc);
}

__global__ __launch_bounds__(256) void k_att(const int* __restrict__ cid){
    int warp = threadIdx.x>>5, lane = threadIdx.x&31;
    int a = blockIdx.x*8 + warp;
    if(a >= N_) return;
    int id = cid[a];
    float x0 = g_x[(size_t)a*64 + lane],     x1 = g_x[(size_t)a*64 + 32 + lane];
    float c0 = g_cm2[id*64 + lane],          c1 = g_cm2[id*64 + 32 + lane];
    float p = x0*c0 + x1*c1;
    #pragma unroll
    for(int o=16;o;o>>=1) p += __shfl_xor_sync(0xffffffffu, p, o);
    float s = sigmoid_acc(p);
    atomicAdd(&g_asum[id*64 + lane],      s*x0);
    atomicAdd(&g_asum[id*64 + 32 + lane], s*x1);
}

__global__ void k_head(const float* __restrict__ fc_W, const float* __restrict__ fc_b,
                       const float* __restrict__ out_W, const float* __restrict__ out_b,
                       float* __restrict__ out){
    __shared__ float am[64];
    __shared__ float red[128];
    int cidx = blockIdx.x, t = threadIdx.x;     // 128 threads
    float cnt = fmaxf(g_cnt[cidx], 1.f);
    if(t<64) am[t] = g_asum[cidx*64 + t] / cnt;
    __syncthreads();
    float acc = fc_b[t];
    #pragma unroll
    for(int k=0;k<64;k++) acc += am[k]*fc_W[k*128 + t];
    float sp = (acc > 20.f) ? acc : log1pf(expf(acc));   // softplus
    red[t] = sp * out_W[t];
    __syncthreads();
    for(int s=64; s; s>>=1){ if(t<s) red[t]+=red[t+s]; __syncthreads(); }
    if(t==0) out[cidx] = red[0] + out_b[0];
}

// ---------------- launch ------------------------------------------------------
extern "C" void kernel_launch(void* const* d_in, const int* in_sizes, int n_in,
                              void* d_out, int out_size){
    const float* atom_fea = (const float*)d_in[0];
    const float* nbr_fea  = (const float*)d_in[1];
    const int*   nbr_idx  = (const int*)  d_in[2];
    const int*   cids     = (const int*)  d_in[3];
    const float* emb_W    = (const float*)d_in[4];
    const float* emb_b    = (const float*)d_in[5];
    const float* conv_W   = (const float*)d_in[6];
    const float* conv_b   = (const float*)d_in[7];
    const float* bn1_g    = (const float*)d_in[8];
    const float* bn1_b    = (const float*)d_in[9];
    const float* bn2_g    = (const float*)d_in[10];
    const float* bn2_b    = (const float*)d_in[11];
    const float* W3_W     = (const float*)d_in[12];
    const float* W3_b     = (const float*)d_in[13];
    const float* fc_W     = (const float*)d_in[14];
    const float* fc_b     = (const float*)d_in[15];
    const float* out_W    = (const float*)d_in[16];
    const float* out_b    = (const float*)d_in[17];

    float* out  = (float*)d_out;
    float* xout = nullptr;
    if(out_size >= C_ + N_*F_) xout = out + ((size_t)out_size - (size_t)N_*F_);

    cudaFuncSetAttribute(k_gated, cudaFuncAttributeMaxDynamicSharedMemorySize, SMEM_GATED);
    cudaFuncSetAttribute(k_z,     cudaFuncAttributeMaxDynamicSharedMemorySize, SMEM_Z);

    k_embed<<<1563,256>>>(atom_fea, emb_W, emb_b);
    k_nbrh <<<(int)(((size_t)NM_*KP_ + 255)/256),256>>>(nbr_fea);
    for(int L=0; L<3; L++){
        k_prep <<<64,256>>>(conv_W, L);
        k_z    <<<dim3(782,2),256,SMEM_Z>>>();
        k_gated<<<9375,256,SMEM_GATED>>>(nbr_idx, conv_b, L);
        k_bn1fin<<<1,128>>>(bn1_g, bn1_b, L);
        k_gatesum<<<1563,256>>>();
        k_bn2fin<<<1,64>>>(bn2_g, bn2_b, L);
        k_update<<<6250,256>>>((L==2) ? xout : nullptr);
    }
    k_zero_pool<<<512,256>>>();
    k_pool1 <<<25000,256>>>(cids);
    k_poolW3<<<2000,64>>>(W3_W, W3_b);
    k_att   <<<12500,256>>>(cids);
    k_head  <<<2000,128>>>(fc_W, fc_b, out_W, out_b, out);
}

// round 15
// speedup vs baseline: 1.4855x; 1.0199x over previous
#include <cuda_runtime.h>
#include <cuda_fp16.h>
#include <cstdint>

#define N_     100000
#define M_     12
#define C_     2000
#define ORIG_  92
#define NBR_   41
#define KP_    48                     // padded K for HMMA (3 x k16)
#define F_     64
#define H_     128
#define EPS_   1e-5f
#define NM_    (N_*M_)

// smem strides (halfs) chosen for conflict-free fragment access
#define SA_STR 56
#define SC_STR 136
#define SMEM_GATED ((128*SA_STR + 128*SA_STR + 128*SC_STR)*2 + 256*4)
#define SAZ_STR 72
#define SMEM_Z  ((128*SAZ_STR + 128*SAZ_STR + 128*SC_STR)*2)

// ---------------- scratch (device globals; no allocations allowed) -----------
__device__ float  g_x[(size_t)N_*F_];          // 25.6 MB  atom features fp32 (pooling)
__device__ __half g_xh[(size_t)N_*F_];         // 12.8 MB  atom features fp16 (GEMM A)
__device__ __half g_zh[(size_t)N_*256];        // 51.2 MB  [x@Wself | x@Wnbr] fp16
__device__ __half g_gated[(size_t)NM_*128];    // 307.2 MB pre-activation gated (fp16)
__device__ __half g_nbrh[(size_t)NM_*KP_];     // 115.2 MB nbr_fea fp16, K padded to 48
__device__ __half g_WchT[128*KP_];             // per-layer conv weight (nbr part), [n][k] fp16
__device__ __half g_WbigT[256*64];             // per-layer packed weight, [n][k] fp16
__device__ float  g_ns[(size_t)N_*F_];         // 25.6 MB  nbr_sumed
__device__ float  g_sum1[128], g_sq1[128], g_s1[128], g_h1[128];
__device__ float  g_sum2[64],  g_sq2[64],  g_s2[64],  g_h2[64];
__device__ float  g_csum[C_*F_], g_cnt[C_], g_cm2[C_*F_], g_asum[C_*F_];

struct __align__(16) H8 { __half2 a,b,c,d; };

// ---------------- math helpers -------------------------------------------------
__device__ __forceinline__ float fast_rcp(float d){
    float y = __int_as_float(0x7EF311C3 - __float_as_int(d));
    y = y*(2.0f - d*y);
    y = y*(2.0f - d*y);
    return y;
}
// accurate FFMA-only tanh (used outside the hot gating loop)
__device__ __forceinline__ float tanh_acc(float x){
    float z  = fminf(fmaxf(x, -7.90531110763549805f), 7.90531110763549805f);
    float x2 = z*z;
    float p = fmaf(x2, -2.76076847742355e-16f, 2.00018790482477e-13f);
    p = fmaf(p, x2, -8.60467152213735e-11f);
    p = fmaf(p, x2,  5.12229709037114e-08f);
    p = fmaf(p, x2,  1.48572235717979e-05f);
    p = fmaf(p, x2,  6.37261928875436e-04f);
    p = fmaf(p, x2,  4.89352455891786e-03f);
    p *= z;
    float q = fmaf(x2, 1.19825839466702e-06f, 1.18534705686654e-04f);
    q = fmaf(q, x2, 2.26843463243900e-03f);
    q = fmaf(q, x2, 4.89352518554385e-03f);
    return p * fast_rcp(q);
}
__device__ __forceinline__ float sigmoid_acc(float x){
    return fmaf(tanh_acc(0.5f*x), 0.5f, 0.5f);
}
// fast HW tanh (MUFU.TANH) — gatesum hot loop only
__device__ __forceinline__ float tanh_fast(float x){
    float y; asm("tanh.approx.f32 %0, %1;" : "=f"(y) : "f"(x)); return y;
}
__device__ __forceinline__ float sigmoid_fast(float x){
    return fmaf(tanh_fast(0.5f*x), 0.5f, 0.5f);
}

__device__ __forceinline__ void mma16816(float& c0,float& c1,float& c2,float& c3,
    uint32_t a0,uint32_t a1,uint32_t a2,uint32_t a3,uint32_t b0,uint32_t b1){
    asm volatile("mma.sync.aligned.m16n8k16.row.col.f32.f16.f16.f32 "
        "{%0,%1,%2,%3},{%4,%5,%6,%7},{%8,%9},{%0,%1,%2,%3};"
        : "+f"(c0),"+f"(c1),"+f"(c2),"+f"(c3)
        : "r"(a0),"r"(a1),"r"(a2),"r"(a3),"r"(b0),"r"(b1));
}

// ---------------- embedding: g_x/g_xh = atom_fea @ emb_W + emb_b --------------
__global__ __launch_bounds__(256) void k_embed(const float* __restrict__ A,
                                               const float* __restrict__ B,
                                               const float* __restrict__ bias){
    __shared__ float sA[64][ORIG_];
    __shared__ float sB[ORIG_][64];
    int bm = blockIdx.x*64, tid = threadIdx.x;
    for(int e=tid; e<64*ORIG_; e+=256){ int r=e/ORIG_, k=e%ORIG_; int gr=bm+r;
        sA[r][k] = (gr<N_) ? A[(size_t)gr*ORIG_ + k] : 0.f; }
    for(int e=tid; e<ORIG_*64; e+=256){ int k=e>>6, c=e&63; sB[k][c] = B[k*64+c]; }
    __syncthreads();
    int tx = tid&15, ty = tid>>4;
    float acc[4][4] = {};
    for(int k=0;k<ORIG_;k++){
        float4 bv = *(const float4*)&sB[k][tx*4];
        #pragma unroll
        for(int i=0;i<4;i++){
            float a = sA[ty*4+i][k];
            acc[i][0]+=a*bv.x; acc[i][1]+=a*bv.y; acc[i][2]+=a*bv.z; acc[i][3]+=a*bv.w;
        }
    }
    #pragma unroll
    for(int i=0;i<4;i++){
        int gr = bm + ty*4 + i;
        if(gr<N_){
            float4 v = make_float4(acc[i][0]+bias[tx*4+0], acc[i][1]+bias[tx*4+1],
                                   acc[i][2]+bias[tx*4+2], acc[i][3]+bias[tx*4+3]);
            *(float4*)&g_x[(size_t)gr*64 + tx*4] = v;
            *(__half2*)&g_xh[(size_t)gr*64 + tx*4]     = __floats2half2_rn(v.x,v.y);
            *(__half2*)&g_xh[(size_t)gr*64 + tx*4 + 2] = __floats2half2_rn(v.z,v.w);
        }
    }
}

// ---------------- one-time: nbr_fea -> fp16 padded [NM][48] -------------------
__global__ __launch_bounds__(256) void k_nbrh(const float* __restrict__ nbr_fea){
    size_t e = (size_t)blockIdx.x*256 + threadIdx.x;
    if(e < (size_t)NM_*KP_){
        size_t r = e / KP_; int k = (int)(e - r*KP_);
        g_nbrh[e] = __float2half(k < NBR_ ? nbr_fea[r*NBR_ + k] : 0.f);
    }
}

// -- build fp16 WbigT [256n][64k] + WcT [128n][48k], zero BN1 stats ------------
__global__ void k_prep(const float* __restrict__ conv_W, int L){
    int e = blockIdx.x*256 + threadIdx.x;       // 64 blocks * 256 = 16384
    const float* W = conv_W + (size_t)L*169*128;
    {   // WbigT: n in 0..255, k in 0..63
        int n = e>>6, kk = e&63;
        g_WbigT[e] = __float2half((n<128) ? W[kk*128 + n] : W[(64+kk)*128 + (n-128)]);
    }
    if(e < 128*KP_){
        int n = e / KP_, kk = e - n*KP_;
        const float* Wc = W + 128*128;
        g_WchT[e] = __float2half(kk < NBR_ ? Wc[kk*128 + n] : 0.f);
    }
    if(blockIdx.x==0 && threadIdx.x<128){ g_sum1[threadIdx.x]=0.f; g_sq1[threadIdx.x]=0.f; }
}

// ---- z = x @ Wbig (HMMA): 128 rows x 128 cols per block, K=64 ----------------
__global__ __launch_bounds__(256) void k_z(){
    extern __shared__ __half smem[];
    __half* sA  = smem;                      // [128][SAZ_STR]
    __half* sBT = smem + 128*SAZ_STR;        // [128][SAZ_STR] (n-major, k inner)
    __half* sC  = smem + 2*128*SAZ_STR;      // [128][SC_STR]
    int bm = blockIdx.x*128, cb = blockIdx.y*128, tid = threadIdx.x;
    {   // A tile: 128 rows x 64 halfs (128B rows) from g_xh
        for(int e=tid; e<128*8; e+=256){ int r=e>>3, u=e&7; int gr=bm+r;
            uint4 v = (gr<N_) ? ((const uint4*)(g_xh + (size_t)gr*64))[u]
                              : make_uint4(0,0,0,0);
            *(uint4*)&sA[r*SAZ_STR + u*8] = v; }
        const uint4* srcB = (const uint4*)(g_WbigT + (size_t)cb*64);
        for(int e=tid; e<128*8; e+=256){ int r=e>>3, u=e&7;
            *(uint4*)&sBT[r*SAZ_STR + u*8] = srcB[r*8+u]; }
    }
    __syncthreads();
    {   // each warp: 16 rows x 128 cols, K=64 (4 k16 steps)
        int w = tid>>5, lane = tid&31, g = lane>>2, t = lane&3;
        const __half* sAw = sA + (w*16)*SAZ_STR;
        uint32_t af[4][4];
        #pragma unroll
        for(int kt=0;kt<4;kt++){
            af[kt][0] = *(const uint32_t*)&sAw[ g   *SAZ_STR + kt*16 + 2*t];
            af[kt][1] = *(const uint32_t*)&sAw[(g+8)*SAZ_STR + kt*16 + 2*t];
            af[kt][2] = *(const uint32_t*)&sAw[ g   *SAZ_STR + kt*16 + 2*t + 8];
            af[kt][3] = *(const uint32_t*)&sAw[(g+8)*SAZ_STR + kt*16 + 2*t + 8];
        }
        #pragma unroll
        for(int nt=0;nt<16;nt++){
            float c0=0.f,c1=0.f,c2=0.f,c3=0.f;
            const __half* sBn = sBT + (nt*8+g)*SAZ_STR;
            #pragma unroll
            for(int kt=0;kt<4;kt++){
                uint32_t b0 = *(const uint32_t*)&sBn[kt*16 + 2*t];
                uint32_t b1 = *(const uint32_t*)&sBn[kt*16 + 2*t + 8];
                mma16816(c0,c1,c2,c3, af[kt][0],af[kt][1],af[kt][2],af[kt][3], b0,b1);
            }
            *(__half2*)&sC[(w*16+g  )*SC_STR + nt*8 + 2*t] = __floats2half2_rn(c0,c1);
            *(__half2*)&sC[(w*16+g+8)*SC_STR + nt*8 + 2*t] = __floats2half2_rn(c2,c3);
        }
    }
    __syncthreads();
    int tx = tid&15, ty = tid>>4, cg = tx*8;
    #pragma unroll
    for(int i=0;i<8;i++){
        int rl = ty*8 + i, gr = bm + rl;
        if(gr<N_)
            *(H8*)&g_zh[(size_t)gr*256 + cb + cg] = *(const H8*)&sC[rl*SC_STR + cg];
    }
}

// ---- gated = nbr_fea@W3 (HMMA) + z1[i] + z2h[idx] + b ; BN1 stats ------------
__global__ __launch_bounds__(256) void k_gated(const int* __restrict__ nbr_idx,
                                               const float* __restrict__ conv_b, int L){
    extern __shared__ __half smem[];
    __half* sA  = smem;                     // [128][SA_STR]
    __half* sBT = smem + 128*SA_STR;        // [128][SA_STR] (n-major, k inner)
    __half* sC  = smem + 2*128*SA_STR;      // [128][SC_STR]
    float* ssum = (float*)(smem + 2*128*SA_STR + 128*SC_STR);
    float* ssq  = ssum + 128;
    int bm = blockIdx.x*128, tid = threadIdx.x;
    {   // load A tile (128 x 48 halfs, contiguous 96B rows) and W^T tile
        const uint4* srcA = (const uint4*)(g_nbrh + (size_t)bm*KP_);
        for(int e=tid; e<128*6; e+=256){ int r=e/6, u=e-r*6;
            *(uint4*)&sA[r*SA_STR + u*8] = srcA[r*6+u]; }
        const uint4* srcB = (const uint4*)g_WchT;
        for(int e=tid; e<128*6; e+=256){ int r=e/6, u=e-r*6;
            *(uint4*)&sBT[r*SA_STR + u*8] = srcB[r*6+u]; }
        if(tid<128){ ssum[tid]=0.f; ssq[tid]=0.f; }
    }
    __syncthreads();
    {   // tensor-core GEMM: each warp 16 rows x 128 cols, K=48
        int w = tid>>5, lane = tid&31, g = lane>>2, t = lane&3;
        const __half* sAw = sA + (w*16)*SA_STR;
        uint32_t af[3][4];
        #pragma unroll
        for(int kt=0;kt<3;kt++){
            af[kt][0] = *(const uint32_t*)&sAw[ g   *SA_STR + kt*16 + 2*t];
            af[kt][1] = *(const uint32_t*)&sAw[(g+8)*SA_STR + kt*16 + 2*t];
            af[kt][2] = *(const uint32_t*)&sAw[ g   *SA_STR + kt*16 + 2*t + 8];
            af[kt][3] = *(const uint32_t*)&sAw[(g+8)*SA_STR + kt*16 + 2*t + 8];
        }
        #pragma unroll
        for(int nt=0;nt<16;nt++){
            float c0=0.f,c1=0.f,c2=0.f,c3=0.f;
            const __half* sBn = sBT + (nt*8+g)*SA_STR;
            #pragma unroll
            for(int kt=0;kt<3;kt++){
                uint32_t b0 = *(const uint32_t*)&sBn[kt*16 + 2*t];
                uint32_t b1 = *(const uint32_t*)&sBn[kt*16 + 2*t + 8];
                mma16816(c0,c1,c2,c3, af[kt][0],af[kt][1],af[kt][2],af[kt][3], b0,b1);
            }
            *(__half2*)&sC[(w*16+g  )*SC_STR + nt*8 + 2*t] = __floats2half2_rn(c0,c1);
            *(__half2*)&sC[(w*16+g+8)*SC_STR + nt*8 + 2*t] = __floats2half2_rn(c2,c3);
        }
    }
    __syncthreads();
    // ---- epilogue: add z1 + z2 + bias, store fp16, BN1 stats -----------------
    int tx = tid&15, ty = tid>>4;
    int cg = tx*8;
    float4 bba = *(const float4*)&conv_b[L*128 + cg];
    float4 bbb = *(const float4*)&conv_b[L*128 + cg + 4];
    float ps[8]={0,0,0,0,0,0,0,0}, pq[8]={0,0,0,0,0,0,0,0};
    #pragma unroll
    for(int i=0;i<8;i++){
        int rl  = ty*8 + i;                // local row
        int r   = bm + rl;                 // edge id; NM divisible by 128
        int ia  = r / 12;
        int nid = nbr_idx[r];
        H8 gm = *(const H8*)&sC[rl*SC_STR + cg];
        float2 m0 = __half22float2(gm.a), m1 = __half22float2(gm.b);
        float2 m2 = __half22float2(gm.c), m3 = __half22float2(gm.d);
        H8 z1 = *(const H8*)&g_zh[(size_t)ia*256 + cg];
        float2 z1a = __half22float2(z1.a), z1b = __half22float2(z1.b);
        float2 z1c = __half22float2(z1.c), z1d = __half22float2(z1.d);
        H8 zh = *(const H8*)&g_zh[(size_t)nid*256 + 128 + cg];
        float2 z2a = __half22float2(zh.a), z2b = __half22float2(zh.b);
        float2 z2c = __half22float2(zh.c), z2d = __half22float2(zh.d);
        float v[8];
        v[0]=m0.x+z1a.x+z2a.x+bba.x; v[1]=m0.y+z1a.y+z2a.y+bba.y;
        v[2]=m1.x+z1b.x+z2b.x+bba.z; v[3]=m1.y+z1b.y+z2b.y+bba.w;
        v[4]=m2.x+z1c.x+z2c.x+bbb.x; v[5]=m2.y+z1c.y+z2c.y+bbb.y;
        v[6]=m3.x+z1d.x+z2d.x+bbb.z; v[7]=m3.y+z1d.y+z2d.y+bbb.w;
        H8 h;
        h.a = __floats2half2_rn(v[0],v[1]);
        h.b = __floats2half2_rn(v[2],v[3]);
        h.c = __floats2half2_rn(v[4],v[5]);
        h.d = __floats2half2_rn(v[6],v[7]);
        *(H8*)&g_gated[(size_t)r*128 + cg] = h;
        #pragma unroll
        for(int j=0;j<8;j++){ ps[j]+=v[j]; pq[j]+=v[j]*v[j]; }
    }
    #pragma unroll
    for(int j=0;j<8;j++){
        ps[j] += __shfl_xor_sync(0xffffffffu, ps[j], 16);
        pq[j] += __shfl_xor_sync(0xffffffffu, pq[j], 16);
    }
    if((tid&16)==0){
        #pragma unroll
        for(int j=0;j<8;j++){ atomicAdd(&ssum[cg+j], ps[j]); atomicAdd(&ssq[cg+j], pq[j]); }
    }
    __syncthreads();
    if(tid<128){ atomicAdd(&g_sum1[tid], ssum[tid]); atomicAdd(&g_sq1[tid], ssq[tid]); }
}

// ---------------- finalize BN1 scale/shift; zero BN2 stats --------------------
__global__ void k_bn1fin(const float* __restrict__ bn1_g, const float* __restrict__ bn1_b, int L){
    int c = threadIdx.x;                  // 128 threads
    float inv  = 1.f/(float)NM_;
    float mean = g_sum1[c]*inv;
    float var  = g_sq1[c]*inv - mean*mean;
    float s    = bn1_g[L*128+c]*rsqrtf(var + EPS_);
    g_s1[c] = s; g_h1[c] = bn1_b[L*128+c] - mean*s;
    if(c<64){ g_sum2[c]=0.f; g_sq2[c]=0.f; }
}

// ---------------- gate+sum over M; BN2 stats (MUFU.TANH activations) ----------
__global__ __launch_bounds__(256) void k_gatesum(){
    int c2 = (threadIdx.x & 31)*2, g = threadIdx.x >> 5;     // col pair, atom group
    int a0 = blockIdx.x*64;
    float s1f0=g_s1[c2],    h1f0=g_h1[c2],    s1f1=g_s1[c2+1],    h1f1=g_h1[c2+1];
    float s1c0=g_s1[64+c2], h1c0=g_h1[64+c2], s1c1=g_s1[64+c2+1], h1c1=g_h1[64+c2+1];
    float ps0=0.f, pq0=0.f, ps1=0.f, pq1=0.f;
    for(int t=0;t<8;t++){
        int a = a0 + t*8 + g;
        if(a < N_){
            const __half* gp = g_gated + (size_t)a*12*128;
            float acc0 = 0.f, acc1 = 0.f;
            #pragma unroll
            for(int m=0;m<12;m++){
                float2 f = __half22float2(*(const __half2*)&gp[m*128 + c2]);
                float2 cc= __half22float2(*(const __half2*)&gp[m*128 + 64 + c2]);
                float yf0 = f.x*s1f0 + h1f0, yf1 = f.y*s1f1 + h1f1;
                float yc0 = cc.x*s1c0 + h1c0, yc1 = cc.y*s1c1 + h1c1;
                acc0 += sigmoid_fast(yf0) * tanh_fast(yc0);
                acc1 += sigmoid_fast(yf1) * tanh_fast(yc1);
            }
            *(float2*)&g_ns[(size_t)a*64 + c2] = make_float2(acc0, acc1);
            ps0 += acc0; pq0 += acc0*acc0;
            ps1 += acc1; pq1 += acc1*acc1;
        }
    }
    __shared__ float ssum[64], ssq[64];
    if(threadIdx.x<64){ ssum[threadIdx.x]=0.f; ssq[threadIdx.x]=0.f; }
    __syncthreads();
    atomicAdd(&ssum[c2], ps0);   atomicAdd(&ssq[c2], pq0);
    atomicAdd(&ssum[c2+1], ps1); atomicAdd(&ssq[c2+1], pq1);
    __syncthreads();
    if(threadIdx.x<64){ atomicAdd(&g_sum2[threadIdx.x], ssum[threadIdx.x]);
                        atomicAdd(&g_sq2 [threadIdx.x], ssq [threadIdx.x]); }
}

__global__ void k_bn2fin(const float* __restrict__ bn2_g, const float* __restrict__ bn2_b, int L){
    int c = threadIdx.x;                  // 64 threads
    float inv  = 1.f/(float)N_;
    float mean = g_sum2[c]*inv;
    float var  = g_sq2[c]*inv - mean*mean;
    float s    = bn2_g[L*64+c]*rsqrtf(var + EPS_);
    g_s2[c] = s; g_h2[c] = bn2_b[L*64+c] - mean*s;
}

// ---------------- x = tanh(x + bn2(nbr_sumed)), 4 elems/thread ----------------
__global__ __launch_bounds__(256) void k_update(float* __restrict__ xout){
    int base = (blockIdx.x*256 + threadIdx.x)*4;   // N*F = 6.4M = 6250*1024 exactly
    int c = base & 63;
    float4 xv = *(const float4*)&g_x[base];
    float4 nv = *(const float4*)&g_ns[base];
    float4 s2 = *(const float4*)&g_s2[c];
    float4 h2 = *(const float4*)&g_h2[c];
    float v0 = tanh_acc(xv.x + nv.x*s2.x + h2.x);
    float v1 = tanh_acc(xv.y + nv.y*s2.y + h2.y);
    float v2 = tanh_acc(xv.z + nv.z*s2.z + h2.z);
    float v3 = tanh_acc(xv.w + nv.w*s2.w + h2.w);
    *(float4*)&g_x[base] = make_float4(v0,v1,v2,v3);
    *(__half2*)&g_xh[base]     = __floats2half2_rn(v0,v1);
    *(__half2*)&g_xh[base + 2] = __floats2half2_rn(v2,v3);
    if(xout) *(float4*)&xout[base] = make_float4(v0,v1,v2,v3);
}

// ---------------- pooling -----------------------------------------------------
__global__ void k_zero_pool(){
    for(int i = blockIdx.x*256 + threadIdx.x; i < C_*F_; i += gridDim.x*256){
        g_csum[i]=0.f; g_asum[i]=0.f;
        if(i<C_) g_cnt[i]=0.f;
    }
}

__global__ __launch_bounds__(256) void k_pool1(const int* __restrict__ cid){
    int idx = blockIdx.x*256 + threadIdx.x;
    if(idx < N_*F_){
        int a = idx>>6, c = idx&63;
        int id = cid[a];
        atomicAdd(&g_csum[id*64 + c], g_x[idx]);
        if(c==0) atomicAdd(&g_cnt[id], 1.f);
    }
}

__global__ void k_poolW3(const float* __restrict__ W3_W, const float* __restrict__ W3_b){
    __shared__ float cm[64];
    int cidx = blockIdx.x, t = threadIdx.x;     // 64 threads
    float cnt = fmaxf(g_cnt[cidx], 1.f);
    cm[t] = g_csum[cidx*64 + t] / cnt;
    __syncthreads();
    float acc = W3_b[t];
    #pragma unroll
    for(int k=0;k<64;k++) acc += cm[k]*W3_W[k*64 + t];
    g_cm2[cidx*64 + t] = tanh_acc(acc);
}

__global__ __launch_bounds__(256) void k_att(const int* __restrict__ cid){
    int warp = threadIdx.x>>5, lane = threadIdx.x&31;
    int a = blockIdx.x*8 + warp;
    if(a >= N_) return;
    int id = cid[a];
    float x0 = g_x[(size_t)a*64 + lane],     x1 = g_x[(size_t)a*64 + 32 + lane];
    float c0 = g_cm2[id*64 + lane],          c1 = g_cm2[id*64 + 32 + lane];
    float p = x0*c0 + x1*c1;
    #pragma unroll
    for(int o=16;o;o>>=1) p += __shfl_xor_sync(0xffffffffu, p, o);
    float s = sigmoid_acc(p);
    atomicAdd(&g_asum[id*64 + lane],      s*x0);
    atomicAdd(&g_asum[id*64 + 32 + lane], s*x1);
}

__global__ void k_head(const float* __restrict__ fc_W, const float* __restrict__ fc_b,
                       const float* __restrict__ out_W, const float* __restrict__ out_b,
                       float* __restrict__ out){
    __shared__ float am[64];
    __shared__ float red[128];
    int cidx = blockIdx.x, t = threadIdx.x;     // 128 threads
    float cnt = fmaxf(g_cnt[cidx], 1.f);
    if(t<64) am[t] = g_asum[cidx*64 + t] / cnt;
    __syncthreads();
    float acc = fc_b[t];
    #pragma unroll
    for(int k=0;k<64;k++) acc += am[k]*fc_W[k*128 + t];
    float sp = (acc > 20.f) ? acc : log1pf(expf(acc));   // softplus
    red[t] = sp * out_W[t];
    __syncthreads();
    for(int s=64; s; s>>=1){ if(t<s) red[t]+=red[t+s]; __syncthreads(); }
    if(t==0) out[cidx] = red[0] + out_b[0];
}

// ---------------- launch ------------------------------------------------------
extern "C" void kernel_launch(void* const* d_in, const int* in_sizes, int n_in,
                              void* d_out, int out_size){
    const float* atom_fea = (const float*)d_in[0];
    const float* nbr_fea  = (const float*)d_in[1];
    const int*   nbr_idx  = (const int*)  d_in[2];
    const int*   cids     = (const int*)  d_in[3];
    const float* emb_W    = (const float*)d_in[4];
    const float* emb_b    = (const float*)d_in[5];
    const float* conv_W   = (const float*)d_in[6];
    const float* conv_b   = (const float*)d_in[7];
    const float* bn1_g    = (const float*)d_in[8];
    const float* bn1_b    = (const float*)d_in[9];
    const float* bn2_g    = (const float*)d_in[10];
    const float* bn2_b    = (const float*)d_in[11];
    const float* W3_W     = (const float*)d_in[12];
    const float* W3_b     = (const float*)d_in[13];
    const float* fc_W     = (const float*)d_in[14];
    const float* fc_b     = (const float*)d_in[15];
    const float* out_W    = (const float*)d_in[16];
    const float* out_b    = (const float*)d_in[17];

    float* out  = (float*)d_out;
    float* xout = nullptr;
    if(out_size >= C_ + N_*F_) xout = out + ((size_t)out_size - (size_t)N_*F_);

    cudaFuncSetAttribute(k_gated, cudaFuncAttributeMaxDynamicSharedMemorySize, SMEM_GATED);
    cudaFuncSetAttribute(k_z,     cudaFuncAttributeMaxDynamicSharedMemorySize, SMEM_Z);

    k_embed<<<1563,256>>>(atom_fea, emb_W, emb_b);
    k_nbrh <<<(int)(((size_t)NM_*KP_ + 255)/256),256>>>(nbr_fea);
    for(int L=0; L<3; L++){
        k_prep <<<64,256>>>(conv_W, L);
        k_z    <<<dim3(782,2),256,SMEM_Z>>>();
        k_gated<<<9375,256,SMEM_GATED>>>(nbr_idx, conv_b, L);
        k_bn1fin<<<1,128>>>(bn1_g, bn1_b, L);
        k_gatesum<<<1563,256>>>();
        k_bn2fin<<<1,64>>>(bn2_g, bn2_b, L);
        k_update<<<6250,256>>>((L==2) ? xout : nullptr);
    }
    k_zero_pool<<<512,256>>>();
    k_pool1 <<<25000,256>>>(cids);
    k_poolW3<<<2000,64>>>(W3_W, W3_b);
    k_att   <<<12500,256>>>(cids);
    k_head  <<<2000,128>>>(fc_W, fc_b, out_W, out_b, out);
}